// round 15
// baseline (speedup 1.0000x reference)
#include <cuda_runtime.h>
#include <cuda_fp16.h>
#include <cstdint>

// LorentzConv1d via single-pass fp16 mma.sync m16n8k16 (fp32 accum).
// Round 15 = r14 (448 thr, persistent warps, K=320 adjacency pair map,
// A via LDS.64, smem-fp32 t_resc) + explicit next-kb B prefetch
// + sqrt.approx + N-permuted output cols (STG.128 stores).
//
// K permutation (K=320, 20 kb x 8 pair-slots):
//   kb = 4*kIdx + jg; pair w of kb = (tap kIdx, ch 16jg + 4(w&3) + 2(w>>2) + {0,1})
//   channel 0 (time) slot multiplies B=0; t_resc is fp32 epilogue rank-1 term.
// N permutation: GEMM logical col (nb, j) -> physical out col 16*(j>>1) + 2nb + (j&1).
//   D thread (q4, s4) holds j = 2s4+e  -> phys col 16s4 + 2nb + e (16 consecutive).
//   B fragment col j = q4g            -> phys n = 16(q4g>>1) + 2nb + (q4g&1).

#define LLEN 8192
#define CIN  64
#define NSM  148
#define NW   14
#define NTHR (NW * 32)                // 448
#define NWTOT (NSM * NW)              // 2072 warps
#define NTILES 4096                   // 16 batches x 256 tiles of 32 rows
#define XQS  40
#define TRW  (36 * XQS)               // fp32 time values, words 1440..1475
#define WPRIV 1480                    // 36*40 xq + 36 trw + 4 pad
#define WB4_OFF (NW * WPRIV)          // 20720 (16B aligned)
#define B_OFF   (WB4_OFF + 160)       // 20880 (16B aligned; wb4 pad to 36 units+pad)
#define LGSTR   81                    // uint4 units per lane slot (20*4 + 1, odd)
#define B_UNITS (32 * LGSTR)          // 2592
#define SMEM_WORDS (B_OFF + B_UNITS * 4)  // 31248
#define SMEM_BYTES (SMEM_WORDS * 4)       // 124992

__device__ __forceinline__ uint32_t h2pack(float a, float b) {
    __half2 h = __floats2half2_rn(a, b);
    return *(uint32_t*)&h;
}
__device__ __forceinline__ float sqrt_approx(float v) {
    float r;
    asm("sqrt.approx.f32 %0, %1;" : "=f"(r) : "f"(v));
    return r;
}
__device__ __forceinline__ void mma_f16(float* d, uint32_t a0, uint32_t a1,
                                        uint32_t a2, uint32_t a3,
                                        uint32_t b0, uint32_t b1) {
    asm volatile(
        "mma.sync.aligned.m16n8k16.row.col.f32.f16.f16.f32 "
        "{%0,%1,%2,%3}, {%4,%5,%6,%7}, {%8,%9}, {%0,%1,%2,%3};"
        : "+f"(d[0]), "+f"(d[1]), "+f"(d[2]), "+f"(d[3])
        : "r"(a0), "r"(a1), "r"(a2), "r"(a3), "r"(b0), "r"(b1));
}
// W weight for (kb, pair w, elem t): tap kIdx = kb>>2, ch = 16jg + 4(w&3) + 2(w>>2) + t
__device__ __forceinline__ float slotW(const float* __restrict__ W, int n,
                                       int kb, int w, int t) {
    int kIdx = kb >> 2;
    int jg   = kb & 3;
    int ch   = 16 * jg + 4 * (w & 3) + 2 * (w >> 2) + t;
    if (ch == 0) return 0.f;          // time channel: zero in GEMM
    return W[(size_t)n * 316 + (ch - 1) * 5 + kIdx + 1];
}

__global__ __launch_bounds__(NTHR, 1)
void lorentz_f16_kernel(const float* __restrict__ x,
                        const float* __restrict__ W,
                        const float* __restrict__ bvec,
                        float* __restrict__ out)
{
    extern __shared__ uint32_t sm[];
    float4* wb4 = (float4*)(sm + WB4_OFF);     // [36] padded stride-9: idx 9*s4+nb
    uint4*  BQ4 = (uint4*)(sm + B_OFF);

    const int tid  = threadIdx.x;
    const int wid  = tid >> 5;
    const int lane = tid & 31;

    // ---- stage B (CTA-shared, once per SM), N-permuted: ----
    // unit (lg, kb, i): lane (q4g, s4g), blocks 2i (x,y) and 2i+1 (z,w)
    //   phys n for block nb = 16*(q4g>>1) + 2*nb + (q4g&1)
    for (int u = tid; u < 32 * 20 * 4; u += NTHR) {
        int i  = u & 3;
        int t2 = u >> 2;
        int kb = t2 % 20;
        int lg = t2 / 20;                      // 0..31
        int q4g = lg >> 2, s4g = lg & 3;
        int n0 = 16 * (q4g >> 1) + (q4g & 1) + 4 * i;   // block 2i
        int n1 = n0 + 2;                                 // block 2i+1
        uint4 w;
        w.x = h2pack(slotW(W, n0, kb, s4g, 0),     slotW(W, n0, kb, s4g, 1));
        w.y = h2pack(slotW(W, n0, kb, s4g + 4, 0), slotW(W, n0, kb, s4g + 4, 1));
        w.z = h2pack(slotW(W, n1, kb, s4g, 0),     slotW(W, n1, kb, s4g, 1));
        w.w = h2pack(slotW(W, n1, kb, s4g + 4, 0), slotW(W, n1, kb, s4g + 4, 1));
        BQ4[lg * LGSTR + kb * 4 + i] = w;
    }
    // ---- fp32 time-weight + bias pairs, per-s4 padded (stride 9): ----
    // wb4[9*s4 + nb] = (W[n,0], b[n], W[n+1,0], b[n+1]), n = 16*s4 + 2*nb
    if (tid < 36) {
        int s4g = tid / 9, nbg = tid - 9 * s4g;
        int n = 16 * s4g + 2 * ((nbg < 8) ? nbg : 0);
        wb4[tid] = make_float4(W[(size_t)n * 316], bvec[n],
                               W[(size_t)(n + 1) * 316], bvec[n + 1]);
    }
    __syncthreads();   // the ONLY CTA-wide barrier

    const int q4 = lane >> 2;
    const int s4 = lane & 3;
    const int wpbase = wid * WPRIV;
    const int bx = wpbase + q4 * XQS + 2 * s4; // A base (word index)
    const int ub = (q4 * 4 + s4) * LGSTR;      // B base (uint4 index)
    const int gw = blockIdx.x * NW + wid;      // global warp id
    float* trw = (float*)(sm + wpbase + TRW);

    // ---- persistent warp loop over 32-row tiles ----
    for (int t = gw; t < NTILES; t += NWTOT) {
        const int bidx = t >> 8;               // 256 tiles per batch
        const int l0   = (t & 255) << 5;
        const float* xb = x + (size_t)bidx * (LLEN * CIN);

        __syncwarp();   // previous tile's xq reads complete before overwrite

        // ---- warp-private xq staging: 36 rows (l0-2 .. l0+33) + fp32 time ----
        {
            const int gbase = l0 - 2;
#pragma unroll
            for (int j = 0; j < 18; j++) {
                int u  = j * 32 + lane;
                int r  = u >> 4, c4 = u & 15;
                int g  = gbase + r;
                float4 v;
                if ((unsigned)g < (unsigned)LLEN) v = *(const float4*)(xb + (size_t)g * CIN + c4 * 4);
                else { v = make_float4(0.f, 0.f, 0.f, 0.f); if (c4 == 0) v.x = 1.0f; }
                uint2 pw;
                pw.x = h2pack(v.x, v.y);
                pw.y = h2pack(v.z, v.w);
                *(uint2*)(sm + wpbase + r * XQS + c4 * 2) = pw;
                if (c4 == 0) trw[r] = v.x;     // exact fp32 time channel
            }
        }
        __syncwarp();

        // ---- mainloop: 20 k-blocks, explicit next-kb B prefetch ----
        float d[2][8][4];
#pragma unroll
        for (int m = 0; m < 2; m++)
#pragma unroll
            for (int nb = 0; nb < 8; nb++)
                d[m][nb][0] = d[m][nb][1] = d[m][nb][2] = d[m][nb][3] = 0.f;

        uint4 b0 = BQ4[ub + 0];
        uint4 b1 = BQ4[ub + 1];
        uint4 b2 = BQ4[ub + 2];
        uint4 b3 = BQ4[ub + 3];

#pragma unroll
        for (int kb = 0; kb < 20; kb++) {
            uint4 c0, c1, c2, c3;
            if (kb < 19) {
                c0 = BQ4[ub + (kb + 1) * 4 + 0];
                c1 = BQ4[ub + (kb + 1) * 4 + 1];
                c2 = BQ4[ub + (kb + 1) * 4 + 2];
                c3 = BQ4[ub + (kb + 1) * 4 + 3];
            }
            const int kIdx = kb >> 2;
            const int jg   = kb & 3;
            const int boff = kIdx * XQS + 8 * jg;

#pragma unroll
            for (int m = 0; m < 2; m++) {
                const int base0 = bx + boff + (16 * m) * XQS;
                uint2 lo = *(const uint2*)(sm + base0);             // {a0, a2}
                uint2 hi = *(const uint2*)(sm + base0 + 8 * XQS);   // {a1, a3}
                mma_f16(d[m][0], lo.x, hi.x, lo.y, hi.y, b0.x, b0.y);
                mma_f16(d[m][1], lo.x, hi.x, lo.y, hi.y, b0.z, b0.w);
                mma_f16(d[m][2], lo.x, hi.x, lo.y, hi.y, b1.x, b1.y);
                mma_f16(d[m][3], lo.x, hi.x, lo.y, hi.y, b1.z, b1.w);
                mma_f16(d[m][4], lo.x, hi.x, lo.y, hi.y, b2.x, b2.y);
                mma_f16(d[m][5], lo.x, hi.x, lo.y, hi.y, b2.z, b2.w);
                mma_f16(d[m][6], lo.x, hi.x, lo.y, hi.y, b3.x, b3.y);
                mma_f16(d[m][7], lo.x, hi.x, lo.y, hi.y, b3.z, b3.w);
            }
            if (kb < 19) { b0 = c0; b1 = c1; b2 = c2; b3 = c3; }
        }

        // ---- epilogue: + W[:,0]*t_resc + b, Lorentz norm, packed STG.128 ----
#pragma unroll
        for (int m = 0; m < 2; m++) {
            const int ra = 16 * m + q4;
            float sa = -4.0f, sb = -4.0f;
#pragma unroll
            for (int k = 0; k < 5; k++) {
                float ta = trw[ra + k];
                float tb = trw[ra + 8 + k];
                sa = fmaf(ta, ta, sa);
                sb = fmaf(tb, tb, sb);
            }
            const float tra = sqrt_approx(sa);
            const float trb = sqrt_approx(sb);
            float ssa = 0.f, ssb = 0.f;
            float4 o0[4], o1[4];               // rows ra, ra+8: cols 16s4..16s4+15
#pragma unroll
            for (int nb = 0; nb < 8; nb++) {
                float4 f4 = wb4[9 * s4 + nb];  // cols 16s4+2nb, +1
                float y0 = fmaf(f4.x, tra, d[m][nb][0]) + f4.y;
                float y1 = fmaf(f4.z, tra, d[m][nb][1]) + f4.w;
                float y2 = fmaf(f4.x, trb, d[m][nb][2]) + f4.y;
                float y3 = fmaf(f4.z, trb, d[m][nb][3]) + f4.w;
                if (!(nb == 0 && s4 == 0)) {   // global col 0 excluded from norm
                    ssa = fmaf(y0, y0, ssa);
                    ssb = fmaf(y2, y2, ssb);
                }
                ssa = fmaf(y1, y1, ssa);
                ssb = fmaf(y3, y3, ssb);
                float* p0 = (float*)&o0[nb >> 1];
                float* p1 = (float*)&o1[nb >> 1];
                p0[2 * (nb & 1) + 0] = y0;
                p0[2 * (nb & 1) + 1] = y1;
                p1[2 * (nb & 1) + 0] = y2;
                p1[2 * (nb & 1) + 1] = y3;
            }
            ssa += __shfl_xor_sync(0xffffffffu, ssa, 1);
            ssa += __shfl_xor_sync(0xffffffffu, ssa, 2);
            ssb += __shfl_xor_sync(0xffffffffu, ssb, 1);
            ssb += __shfl_xor_sync(0xffffffffu, ssb, 2);
            if (s4 == 0) {
                o0[0].x = sqrt_approx(ssa + 1.0f);
                o1[0].x = sqrt_approx(ssb + 1.0f);
            }

            const size_t base = ((size_t)bidx * LLEN + (size_t)(l0 + ra)) * 64 + 16 * s4;
#pragma unroll
            for (int c = 0; c < 4; c++) {
                *(float4*)(out + base + 4 * c)       = o0[c];
                *(float4*)(out + base + 512 + 4 * c) = o1[c];  // row +8
            }
        }
    }
}

extern "C" void kernel_launch(void* const* d_in, const int* in_sizes, int n_in,
                              void* d_out, int out_size)
{
    const float* x = (const float*)d_in[0];
    const float* W = (const float*)d_in[1];
    const float* b = (const float*)d_in[2];
    float* out = (float*)d_out;

    cudaFuncSetAttribute(lorentz_f16_kernel,
                         cudaFuncAttributeMaxDynamicSharedMemorySize, SMEM_BYTES);
    lorentz_f16_kernel<<<NSM, NTHR, SMEM_BYTES>>>(x, W, b, out);
}

// round 16
// speedup vs baseline: 1.0609x; 1.0609x over previous
#include <cuda_runtime.h>
#include <cuda_fp16.h>
#include <cstdint>

// LorentzConv1d via single-pass fp16 mma.sync m16n8k16 (fp32 accum).
// Round 16: ONE 64-row supertile per warp (2048 tiles, 2072 warps, single
// wave -> no mid-kernel staging bubble). 68-row warp-private staging done
// once; two sequential 32-row mainloop+epilogue halves (r14 economics).
// sqrt.approx in epilogue. No prefetch / store-permute (regressed in r15).
//
// K permutation (K=320, 20 kb x 8 pair-slots):
//   kb = 4*kIdx + jg; pair w of kb = (tap kIdx, ch 16jg + 4(w&3) + 2(w>>2) + {0,1})
//   channel 0 (time) slot multiplies B=0; t_resc is fp32 epilogue rank-1 term.
// A tile xq row-major fp16, word c = channels {2c,2c+1}, warp-private, XQS=40:
//   LDS.64 pairs, bank = 8*q4 + 2*s4 + const -> conflict-free per phase.

#define LLEN 8192
#define CIN  64
#define NSM  148
#define NW   14
#define NTHR (NW * 32)                // 448
#define NT64 2048                     // 16 batches x 128 supertiles of 64 rows
#define XQS  40
#define XROWS 68                      // 64 + 4 halo
#define TRW  (XROWS * XQS)            // 2720: fp32 time values
#define WPRIV 2792                    // 2720 xq + 68 trw + 4 pad (16B-aligned)
#define WB4_OFF (NW * WPRIV)          // 39088
#define B_OFF   (WB4_OFF + 128)       // 39216 (16B aligned)
#define LGSTR   81                    // uint4 units per lane slot (20*4 + 1, odd)
#define B_UNITS (32 * LGSTR)          // 2592
#define SMEM_WORDS (B_OFF + B_UNITS * 4)  // 49584
#define SMEM_BYTES (SMEM_WORDS * 4)       // 198336

__device__ __forceinline__ uint32_t h2pack(float a, float b) {
    __half2 h = __floats2half2_rn(a, b);
    return *(uint32_t*)&h;
}
__device__ __forceinline__ float sqrt_approx(float v) {
    float r;
    asm("sqrt.approx.f32 %0, %1;" : "=f"(r) : "f"(v));
    return r;
}
__device__ __forceinline__ void mma_f16(float* d, uint32_t a0, uint32_t a1,
                                        uint32_t a2, uint32_t a3,
                                        uint32_t b0, uint32_t b1) {
    asm volatile(
        "mma.sync.aligned.m16n8k16.row.col.f32.f16.f16.f32 "
        "{%0,%1,%2,%3}, {%4,%5,%6,%7}, {%8,%9}, {%0,%1,%2,%3};"
        : "+f"(d[0]), "+f"(d[1]), "+f"(d[2]), "+f"(d[3])
        : "r"(a0), "r"(a1), "r"(a2), "r"(a3), "r"(b0), "r"(b1));
}
// W weight for (kb, pair w, elem t): tap kIdx = kb>>2, ch = 16jg + 4(w&3) + 2(w>>2) + t
__device__ __forceinline__ float slotW(const float* __restrict__ W, int n,
                                       int kb, int w, int t) {
    int kIdx = kb >> 2;
    int jg   = kb & 3;
    int ch   = 16 * jg + 4 * (w & 3) + 2 * (w >> 2) + t;
    if (ch == 0) return 0.f;          // time channel: zero in GEMM
    return W[(size_t)n * 316 + (ch - 1) * 5 + kIdx + 1];
}

__global__ __launch_bounds__(NTHR, 1)
void lorentz_f16_kernel(const float* __restrict__ x,
                        const float* __restrict__ W,
                        const float* __restrict__ bvec,
                        float* __restrict__ out)
{
    extern __shared__ uint32_t sm[];
    float4* wb4 = (float4*)(sm + WB4_OFF);
    uint4*  BQ4 = (uint4*)(sm + B_OFF);

    const int tid  = threadIdx.x;
    const int wid  = tid >> 5;
    const int lane = tid & 31;

    // ---- stage B (CTA-shared, once per SM): unit (lg, kb, i) ----
    for (int u = tid; u < 32 * 20 * 4; u += NTHR) {
        int i  = u & 3;
        int t2 = u >> 2;
        int kb = t2 % 20;
        int lg = t2 / 20;                      // 0..31
        int q4g = lg >> 2, s4g = lg & 3;
        int n0 = 16 * i + q4g;
        int n1 = n0 + 8;
        uint4 w;
        w.x = h2pack(slotW(W, n0, kb, s4g, 0),     slotW(W, n0, kb, s4g, 1));
        w.y = h2pack(slotW(W, n0, kb, s4g + 4, 0), slotW(W, n0, kb, s4g + 4, 1));
        w.z = h2pack(slotW(W, n1, kb, s4g, 0),     slotW(W, n1, kb, s4g, 1));
        w.w = h2pack(slotW(W, n1, kb, s4g + 4, 0), slotW(W, n1, kb, s4g + 4, 1));
        BQ4[lg * LGSTR + kb * 4 + i] = w;
    }
    // ---- fp32 time-weight + bias pairs ----
    if (tid < 32) {
        wb4[tid] = make_float4(W[(size_t)(2 * tid) * 316], bvec[2 * tid],
                               W[(size_t)(2 * tid + 1) * 316], bvec[2 * tid + 1]);
    }
    __syncthreads();   // the ONLY CTA-wide barrier

    const int gw = blockIdx.x * NW + wid;      // global warp id
    if (gw >= NT64) return;                    // 24 surplus warps exit

    const int q4 = lane >> 2;
    const int s4 = lane & 3;
    const int wpbase = wid * WPRIV;
    const int bx = wpbase + q4 * XQS + 2 * s4; // A base (word index)
    const int ub = (q4 * 4 + s4) * LGSTR;      // B base (uint4 index)
    float* trw = (float*)(sm + wpbase + TRW);

    const int bidx = gw >> 7;                  // 128 supertiles per batch
    const int l0   = (gw & 127) << 6;          // 64 rows per supertile
    const float* xb = x + (size_t)bidx * (LLEN * CIN);

    // ---- warp-private xq staging: 68 rows (l0-2 .. l0+65) + fp32 time ----
    {
        const int gbase = l0 - 2;
#pragma unroll
        for (int j = 0; j < 34; j++) {
            int u  = j * 32 + lane;
            int r  = u >> 4, c4 = u & 15;
            int g  = gbase + r;
            float4 v;
            if ((unsigned)g < (unsigned)LLEN) v = *(const float4*)(xb + (size_t)g * CIN + c4 * 4);
            else { v = make_float4(0.f, 0.f, 0.f, 0.f); if (c4 == 0) v.x = 1.0f; }
            uint2 pw;
            pw.x = h2pack(v.x, v.y);
            pw.y = h2pack(v.z, v.w);
            *(uint2*)(sm + wpbase + r * XQS + c4 * 2) = pw;
            if (c4 == 0) trw[r] = v.x;         // exact fp32 time channel
        }
    }
    __syncwarp();

    // ---- two 32-row halves ----
#pragma unroll 1
    for (int h = 0; h < 2; h++) {
        const int hb = bx + (32 * h) * XQS;

        float d[2][8][4];
#pragma unroll
        for (int m = 0; m < 2; m++)
#pragma unroll
            for (int nb = 0; nb < 8; nb++)
                d[m][nb][0] = d[m][nb][1] = d[m][nb][2] = d[m][nb][3] = 0.f;

#pragma unroll
        for (int kb = 0; kb < 20; kb++) {
            const int kIdx = kb >> 2;
            const int jg   = kb & 3;
            const int boff = kIdx * XQS + 8 * jg;

            uint4 b0 = BQ4[ub + kb * 4 + 0];
            uint4 b1 = BQ4[ub + kb * 4 + 1];
            uint4 b2 = BQ4[ub + kb * 4 + 2];
            uint4 b3 = BQ4[ub + kb * 4 + 3];

#pragma unroll
            for (int m = 0; m < 2; m++) {
                const int base0 = hb + boff + (16 * m) * XQS;
                uint2 lo = *(const uint2*)(sm + base0);             // {a0, a2}
                uint2 hi = *(const uint2*)(sm + base0 + 8 * XQS);   // {a1, a3}
                mma_f16(d[m][0], lo.x, hi.x, lo.y, hi.y, b0.x, b0.y);
                mma_f16(d[m][1], lo.x, hi.x, lo.y, hi.y, b0.z, b0.w);
                mma_f16(d[m][2], lo.x, hi.x, lo.y, hi.y, b1.x, b1.y);
                mma_f16(d[m][3], lo.x, hi.x, lo.y, hi.y, b1.z, b1.w);
                mma_f16(d[m][4], lo.x, hi.x, lo.y, hi.y, b2.x, b2.y);
                mma_f16(d[m][5], lo.x, hi.x, lo.y, hi.y, b2.z, b2.w);
                mma_f16(d[m][6], lo.x, hi.x, lo.y, hi.y, b3.x, b3.y);
                mma_f16(d[m][7], lo.x, hi.x, lo.y, hi.y, b3.z, b3.w);
            }
        }

        // ---- epilogue: + W[:,0]*t_resc + b, Lorentz norm (in-warp over s4), store ----
#pragma unroll
        for (int m = 0; m < 2; m++) {
            const int ra = 32 * h + 16 * m + q4;     // local row in supertile
            float sa = -4.0f, sb = -4.0f;
#pragma unroll
            for (int k = 0; k < 5; k++) {
                float ta = trw[ra + k];
                float tb = trw[ra + 8 + k];
                sa = fmaf(ta, ta, sa);
                sb = fmaf(tb, tb, sb);
            }
            const float tra = sqrt_approx(sa);
            const float trb = sqrt_approx(sb);
            float ssa = 0.f, ssb = 0.f;
#pragma unroll
            for (int nb = 0; nb < 8; nb++) {
                float4 f4 = wb4[nb * 4 + s4];
                float y0 = fmaf(f4.x, tra, d[m][nb][0]) + f4.y;
                float y1 = fmaf(f4.z, tra, d[m][nb][1]) + f4.w;
                float y2 = fmaf(f4.x, trb, d[m][nb][2]) + f4.y;
                float y3 = fmaf(f4.z, trb, d[m][nb][3]) + f4.w;
                if (!(nb == 0 && s4 == 0)) {   // global col 0 excluded from the norm
                    ssa = fmaf(y0, y0, ssa);
                    ssb = fmaf(y2, y2, ssb);
                }
                ssa = fmaf(y1, y1, ssa);
                ssb = fmaf(y3, y3, ssb);
                d[m][nb][0] = y0; d[m][nb][1] = y1;
                d[m][nb][2] = y2; d[m][nb][3] = y3;
            }
            ssa += __shfl_xor_sync(0xffffffffu, ssa, 1);
            ssa += __shfl_xor_sync(0xffffffffu, ssa, 2);
            ssb += __shfl_xor_sync(0xffffffffu, ssb, 1);
            ssb += __shfl_xor_sync(0xffffffffu, ssb, 2);
            if (s4 == 0) {
                d[m][0][0] = sqrt_approx(ssa + 1.0f);
                d[m][0][2] = sqrt_approx(ssb + 1.0f);
            }

            const size_t oa = ((size_t)bidx * LLEN + (size_t)(l0 + ra)) * 64 + 2 * s4;
            const size_t ob = oa + 8 * 64;
#pragma unroll
            for (int nb = 0; nb < 8; nb++) {
                *(float2*)(out + oa + nb * 8) = make_float2(d[m][nb][0], d[m][nb][1]);
                *(float2*)(out + ob + nb * 8) = make_float2(d[m][nb][2], d[m][nb][3]);
            }
        }
    }
}

extern "C" void kernel_launch(void* const* d_in, const int* in_sizes, int n_in,
                              void* d_out, int out_size)
{
    const float* x = (const float*)d_in[0];
    const float* W = (const float*)d_in[1];
    const float* b = (const float*)d_in[2];
    float* out = (float*)d_out;

    cudaFuncSetAttribute(lorentz_f16_kernel,
                         cudaFuncAttributeMaxDynamicSharedMemorySize, SMEM_BYTES);
    lorentz_f16_kernel<<<NSM, NTHR, SMEM_BYTES>>>(x, W, b, out);
}

// round 17
// speedup vs baseline: 1.0714x; 1.0099x over previous
#include <cuda_runtime.h>
#include <cuda_fp16.h>
#include <cstdint>

// LorentzConv1d via single-pass fp16 mma.sync m16n8k16 (fp32 accum).
// Round 17 = r14 base (448 thr, 14 warps, persistent 2x32-row tiles) with a
// jg-outer / kIdx-inner mainloop: A row-regs loaded ONCE per jg (5 LDS.64),
// tap-shifted fragments for kIdx=1..4 derived via shfl.sync + select
// (conv row-reuse exploited in registers -> A smem traffic / 4).
//
// K permutation (K=320, 20 kb x 8 pair-slots):
//   kb = 4*kIdx + jg; pair w of kb = (tap kIdx, ch 16jg + 4(w&3) + 2(w>>2) + {0,1})
//   channel 0 (time) slot multiplies B=0; t_resc is fp32 epilogue rank-1 term.
// A tile xq row-major fp16 (word c = channels {2c,2c+1}), warp-private, XQS=40.
// Row-slot regs R[i] = words {8jg+2s4, +1} of row q4+8i (i=0..4, slot 4 = halo).
// Fragment (kIdx, m): src lane (lane+4kIdx)&31; slot 2m(+1) if q4+kIdx<8 else +1.

#define LLEN 8192
#define CIN  64
#define NSM  148
#define NW   14
#define NTHR (NW * 32)                // 448
#define NWTOT (NSM * NW)              // 2072 warps
#define NTILES 4096                   // 16 batches x 256 tiles of 32 rows
#define XQS  40
#define TRW  (36 * XQS)               // fp32 time values, words 1440..1475
#define WPRIV 1480                    // 36*40 xq + 36 trw + 4 pad
#define WB4_OFF (NW * WPRIV)          // 20720 (16B aligned)
#define B_OFF   (WB4_OFF + 128)       // 20848 (16B aligned)
#define LGSTR   81                    // uint4 units per lane slot (20*4 + 1, odd)
#define B_UNITS (32 * LGSTR)          // 2592
#define SMEM_WORDS (B_OFF + B_UNITS * 4)  // 31216
#define SMEM_BYTES (SMEM_WORDS * 4)       // 124864

__device__ __forceinline__ uint32_t h2pack(float a, float b) {
    __half2 h = __floats2half2_rn(a, b);
    return *(uint32_t*)&h;
}
__device__ __forceinline__ float sqrt_approx(float v) {
    float r;
    asm("sqrt.approx.f32 %0, %1;" : "=f"(r) : "f"(v));
    return r;
}
__device__ __forceinline__ void mma_f16(float* d, uint32_t a0, uint32_t a1,
                                        uint32_t a2, uint32_t a3,
                                        uint32_t b0, uint32_t b1) {
    asm volatile(
        "mma.sync.aligned.m16n8k16.row.col.f32.f16.f16.f32 "
        "{%0,%1,%2,%3}, {%4,%5,%6,%7}, {%8,%9}, {%0,%1,%2,%3};"
        : "+f"(d[0]), "+f"(d[1]), "+f"(d[2]), "+f"(d[3])
        : "r"(a0), "r"(a1), "r"(a2), "r"(a3), "r"(b0), "r"(b1));
}
// W weight for (kb, pair w, elem t): tap kIdx = kb>>2, ch = 16jg + 4(w&3) + 2(w>>2) + t
__device__ __forceinline__ float slotW(const float* __restrict__ W, int n,
                                       int kb, int w, int t) {
    int kIdx = kb >> 2;
    int jg   = kb & 3;
    int ch   = 16 * jg + 4 * (w & 3) + 2 * (w >> 2) + t;
    if (ch == 0) return 0.f;          // time channel: zero in GEMM
    return W[(size_t)n * 316 + (ch - 1) * 5 + kIdx + 1];
}

__global__ __launch_bounds__(NTHR, 1)
void lorentz_f16_kernel(const float* __restrict__ x,
                        const float* __restrict__ W,
                        const float* __restrict__ bvec,
                        float* __restrict__ out)
{
    extern __shared__ uint32_t sm[];
    float4* wb4 = (float4*)(sm + WB4_OFF);
    uint4*  BQ4 = (uint4*)(sm + B_OFF);

    const int tid  = threadIdx.x;
    const int wid  = tid >> 5;
    const int lane = tid & 31;

    // ---- stage B (CTA-shared, once per SM): unit (lg, kb, i) ----
    for (int u = tid; u < 32 * 20 * 4; u += NTHR) {
        int i  = u & 3;
        int t2 = u >> 2;
        int kb = t2 % 20;
        int lg = t2 / 20;                      // 0..31
        int q4g = lg >> 2, s4g = lg & 3;
        int n0 = 16 * i + q4g;
        int n1 = n0 + 8;
        uint4 w;
        w.x = h2pack(slotW(W, n0, kb, s4g, 0),     slotW(W, n0, kb, s4g, 1));
        w.y = h2pack(slotW(W, n0, kb, s4g + 4, 0), slotW(W, n0, kb, s4g + 4, 1));
        w.z = h2pack(slotW(W, n1, kb, s4g, 0),     slotW(W, n1, kb, s4g, 1));
        w.w = h2pack(slotW(W, n1, kb, s4g + 4, 0), slotW(W, n1, kb, s4g + 4, 1));
        BQ4[lg * LGSTR + kb * 4 + i] = w;
    }
    // ---- fp32 time-weight + bias pairs ----
    if (tid < 32) {
        wb4[tid] = make_float4(W[(size_t)(2 * tid) * 316], bvec[2 * tid],
                               W[(size_t)(2 * tid + 1) * 316], bvec[2 * tid + 1]);
    }
    __syncthreads();   // the ONLY CTA-wide barrier

    const int q4 = lane >> 2;
    const int s4 = lane & 3;
    const int wpbase = wid * WPRIV;
    const int ub = (q4 * 4 + s4) * LGSTR;      // B base (uint4 index)
    const int gw = blockIdx.x * NW + wid;      // global warp id
    float* trw = (float*)(sm + wpbase + TRW);

    // ---- persistent warp loop over 32-row tiles ----
    for (int t = gw; t < NTILES; t += NWTOT) {
        const int bidx = t >> 8;               // 256 tiles per batch
        const int l0   = (t & 255) << 5;
        const float* xb = x + (size_t)bidx * (LLEN * CIN);

        __syncwarp();   // previous tile's xq reads complete before overwrite

        // ---- warp-private xq staging: 36 rows (l0-2 .. l0+33) + fp32 time ----
        {
            const int gbase = l0 - 2;
#pragma unroll
            for (int j = 0; j < 18; j++) {
                int u  = j * 32 + lane;
                int r  = u >> 4, c4 = u & 15;
                int g  = gbase + r;
                float4 v;
                if ((unsigned)g < (unsigned)LLEN) v = *(const float4*)(xb + (size_t)g * CIN + c4 * 4);
                else { v = make_float4(0.f, 0.f, 0.f, 0.f); if (c4 == 0) v.x = 1.0f; }
                uint2 pw;
                pw.x = h2pack(v.x, v.y);
                pw.y = h2pack(v.z, v.w);
                *(uint2*)(sm + wpbase + r * XQS + c4 * 2) = pw;
                if (c4 == 0) trw[r] = v.x;     // exact fp32 time channel
            }
        }
        __syncwarp();

        // ---- mainloop: jg outer, kIdx inner; A row-regs + tap-shift shuffles ----
        float d[2][8][4];
#pragma unroll
        for (int m = 0; m < 2; m++)
#pragma unroll
            for (int nb = 0; nb < 8; nb++)
                d[m][nb][0] = d[m][nb][1] = d[m][nb][2] = d[m][nb][3] = 0.f;

#pragma unroll
        for (int jg = 0; jg < 4; jg++) {
            // row-slot regs: R[i] = words {8jg+2s4, +1} of row q4+8i
            uint32_t Rp0[5], Rp1[5];
            {
                const int cb = wpbase + 8 * jg + 2 * s4;
#pragma unroll
                for (int i = 0; i < 5; i++) {
                    int rr = q4 + 8 * i;
                    if (rr > 35) rr = 35;      // clamp (lanes whose slot-4 is never consumed)
                    uint2 v = *(const uint2*)(sm + cb + rr * XQS);
                    Rp0[i] = v.x; Rp1[i] = v.y;
                }
            }

#pragma unroll
            for (int kIdx = 0; kIdx < 5; kIdx++) {
                const int kb = 4 * kIdx + jg;
                uint4 b0 = BQ4[ub + kb * 4 + 0];
                uint4 b1 = BQ4[ub + kb * 4 + 1];
                uint4 b2 = BQ4[ub + kb * 4 + 2];
                uint4 b3 = BQ4[ub + kb * 4 + 3];

                uint32_t a[2][4];              // [m][a0,a1,a2,a3]
                if (kIdx == 0) {
                    a[0][0] = Rp0[0]; a[0][1] = Rp0[1]; a[0][2] = Rp1[0]; a[0][3] = Rp1[1];
                    a[1][0] = Rp0[2]; a[1][1] = Rp0[3]; a[1][2] = Rp1[2]; a[1][3] = Rp1[3];
                } else {
                    const int  src = (lane + 4 * kIdx) & 31;
                    const bool hi  = (q4 + kIdx) >= 8;
                    uint32_t S0 = __shfl_sync(0xffffffffu, Rp0[0], src);
                    uint32_t S1 = __shfl_sync(0xffffffffu, Rp0[1], src);
                    uint32_t S2 = __shfl_sync(0xffffffffu, Rp0[2], src);
                    uint32_t S3 = __shfl_sync(0xffffffffu, Rp0[3], src);
                    uint32_t S4 = __shfl_sync(0xffffffffu, Rp0[4], src);
                    uint32_t T0 = __shfl_sync(0xffffffffu, Rp1[0], src);
                    uint32_t T1 = __shfl_sync(0xffffffffu, Rp1[1], src);
                    uint32_t T2 = __shfl_sync(0xffffffffu, Rp1[2], src);
                    uint32_t T3 = __shfl_sync(0xffffffffu, Rp1[3], src);
                    uint32_t T4 = __shfl_sync(0xffffffffu, Rp1[4], src);
                    a[0][0] = hi ? S1 : S0;    // row q4+kIdx
                    a[0][1] = hi ? S2 : S1;    // row q4+kIdx+8
                    a[0][2] = hi ? T1 : T0;
                    a[0][3] = hi ? T2 : T1;
                    a[1][0] = hi ? S3 : S2;    // row q4+kIdx+16
                    a[1][1] = hi ? S4 : S3;    // row q4+kIdx+24
                    a[1][2] = hi ? T3 : T2;
                    a[1][3] = hi ? T4 : T3;
                }

#pragma unroll
                for (int m = 0; m < 2; m++) {
                    mma_f16(d[m][0], a[m][0], a[m][1], a[m][2], a[m][3], b0.x, b0.y);
                    mma_f16(d[m][1], a[m][0], a[m][1], a[m][2], a[m][3], b0.z, b0.w);
                    mma_f16(d[m][2], a[m][0], a[m][1], a[m][2], a[m][3], b1.x, b1.y);
                    mma_f16(d[m][3], a[m][0], a[m][1], a[m][2], a[m][3], b1.z, b1.w);
                    mma_f16(d[m][4], a[m][0], a[m][1], a[m][2], a[m][3], b2.x, b2.y);
                    mma_f16(d[m][5], a[m][0], a[m][1], a[m][2], a[m][3], b2.z, b2.w);
                    mma_f16(d[m][6], a[m][0], a[m][1], a[m][2], a[m][3], b3.x, b3.y);
                    mma_f16(d[m][7], a[m][0], a[m][1], a[m][2], a[m][3], b3.z, b3.w);
                }
            }
        }

        // ---- epilogue: + W[:,0]*t_resc + b, Lorentz norm (in-warp over s4), store ----
#pragma unroll
        for (int m = 0; m < 2; m++) {
            const int ra = 16 * m + q4;
            float sa = -4.0f, sb = -4.0f;
#pragma unroll
            for (int k = 0; k < 5; k++) {
                float ta = trw[ra + k];
                float tb = trw[ra + 8 + k];
                sa = fmaf(ta, ta, sa);
                sb = fmaf(tb, tb, sb);
            }
            const float tra = sqrt_approx(sa);
            const float trb = sqrt_approx(sb);
            float ssa = 0.f, ssb = 0.f;
#pragma unroll
            for (int nb = 0; nb < 8; nb++) {
                float4 f4 = wb4[nb * 4 + s4];
                float y0 = fmaf(f4.x, tra, d[m][nb][0]) + f4.y;
                float y1 = fmaf(f4.z, tra, d[m][nb][1]) + f4.w;
                float y2 = fmaf(f4.x, trb, d[m][nb][2]) + f4.y;
                float y3 = fmaf(f4.z, trb, d[m][nb][3]) + f4.w;
                if (!(nb == 0 && s4 == 0)) {   // global col 0 excluded from the norm
                    ssa = fmaf(y0, y0, ssa);
                    ssb = fmaf(y2, y2, ssb);
                }
                ssa = fmaf(y1, y1, ssa);
                ssb = fmaf(y3, y3, ssb);
                d[m][nb][0] = y0; d[m][nb][1] = y1;
                d[m][nb][2] = y2; d[m][nb][3] = y3;
            }
            ssa += __shfl_xor_sync(0xffffffffu, ssa, 1);
            ssa += __shfl_xor_sync(0xffffffffu, ssa, 2);
            ssb += __shfl_xor_sync(0xffffffffu, ssb, 1);
            ssb += __shfl_xor_sync(0xffffffffu, ssb, 2);
            if (s4 == 0) {
                d[m][0][0] = sqrt_approx(ssa + 1.0f);
                d[m][0][2] = sqrt_approx(ssb + 1.0f);
            }

            const size_t oa = ((size_t)bidx * LLEN + (size_t)(l0 + ra)) * 64 + 2 * s4;
            const size_t ob = oa + 8 * 64;
#pragma unroll
            for (int nb = 0; nb < 8; nb++) {
                *(float2*)(out + oa + nb * 8) = make_float2(d[m][nb][0], d[m][nb][1]);
                *(float2*)(out + ob + nb * 8) = make_float2(d[m][nb][2], d[m][nb][3]);
            }
        }
    }
}

extern "C" void kernel_launch(void* const* d_in, const int* in_sizes, int n_in,
                              void* d_out, int out_size)
{
    const float* x = (const float*)d_in[0];
    const float* W = (const float*)d_in[1];
    const float* b = (const float*)d_in[2];
    float* out = (float*)d_out;

    cudaFuncSetAttribute(lorentz_f16_kernel,
                         cudaFuncAttributeMaxDynamicSharedMemorySize, SMEM_BYTES);
    lorentz_f16_kernel<<<NSM, NTHR, SMEM_BYTES>>>(x, W, b, out);
}